// round 13
// baseline (speedup 1.0000x reference)
#include <cuda_runtime.h>
#include <cuda_bf16.h>
#include <math.h>
#include <stdint.h>

#define DEV_INLINE __device__ __forceinline__

// Problem constants
constexpr int Bc = 4, Tc = 200, Uc = 100, U1 = 101, Hc = 320, IN = 512, Vc = 1000;
constexpr int ROWS_B = Tc * U1;                    // 20200 rows (t,u) per batch
constexpr int MT = 64;                             // rows per CTA
constexpr int VPAD = 1024;                         // V padded to 8x128
constexpr int BLKS_B = (ROWS_B + MT - 1) / MT;     // 316

constexpr int ASB = 528;                           // A row stride BYTES (512 + 16)
constexpr int BSB = 144;                           // B row stride BYTES (128 + 16)
constexpr int A_BYTES = MT * ASB;                  // 33792
constexpr int B_BYTES = 128 * BSB;                 // 18432
constexpr int DSMEM = A_BYTES + 2 * B_BYTES;       // 70656
constexpr int NCHUNK = 32;                         // 8 ntiles x 4 kchunks(128 fp8)
constexpr float SCALE_INV = 1.0f / 256.0f;         // (16*h)*(16*w) -> /256

// Scratch (no allocations allowed -> device globals)
__device__ __align__(16) float g_henc[Bc * Tc * IN];
__device__ __align__(16) float g_hdec[Bc * U1 * IN];
__device__ __align__(16) uint8_t g_W2q[VPAD * IN];   // fp8(16*W2^T) [v][k]
__device__ __align__(16) float g_blank[Bc * Tc * U1];
__device__ __align__(16) float g_label[Bc * Tc * Uc];
__device__ float g_ll[Bc];
__device__ int g_done;                               // zero-init; winner resets

// ---------------------------------------------------------------------------
// Helpers
// ---------------------------------------------------------------------------
DEV_INLINE float tanh_approx(float x) {
    float y; asm("tanh.approx.f32 %0, %1;" : "=f"(y) : "f"(x)); return y;
}
DEV_INLINE uint32_t smemu32(const void* p) {
    uint32_t a;
    asm("{ .reg .u64 t; cvta.to.shared.u64 t, %1; cvt.u32.u64 %0, t; }" : "=r"(a) : "l"(p));
    return a;
}
DEV_INLINE void cp_async16(uint32_t dst, const void* src) {
    asm volatile("cp.async.ca.shared.global [%0], [%1], 16;"
                 :: "r"(dst), "l"(src) : "memory");
}
DEV_INLINE void cp_commit() { asm volatile("cp.async.commit_group;" ::: "memory"); }
DEV_INLINE void cp_wait0()  { asm volatile("cp.async.wait_group 0;" ::: "memory"); }

DEV_INLINE void ldmx4(uint32_t addr, uint32_t& r0, uint32_t& r1, uint32_t& r2, uint32_t& r3) {
    asm volatile("ldmatrix.sync.aligned.m8n8.x4.shared.b16 {%0,%1,%2,%3}, [%4];"
                 : "=r"(r0), "=r"(r1), "=r"(r2), "=r"(r3) : "r"(addr));
}
DEV_INLINE void mma_fp8(float& c0, float& c1, float& c2, float& c3,
                        uint32_t a0, uint32_t a1, uint32_t a2, uint32_t a3,
                        uint32_t b0, uint32_t b1) {
    asm volatile(
        "mma.sync.aligned.m16n8k32.row.col.f32.e4m3.e4m3.f32 "
        "{%0,%1,%2,%3}, {%4,%5,%6,%7}, {%8,%9}, {%0,%1,%2,%3};"
        : "+f"(c0), "+f"(c1), "+f"(c2), "+f"(c3)
        : "r"(a0), "r"(a1), "r"(a2), "r"(a3), "r"(b0), "r"(b1));
}
DEV_INLINE uint32_t pack_e4m3x4(float f0, float f1, float f2, float f3) {
    uint16_t lo, hi;
    asm("cvt.rn.satfinite.e4m3x2.f32 %0, %1, %2;" : "=h"(lo) : "f"(f1), "f"(f0));
    asm("cvt.rn.satfinite.e4m3x2.f32 %0, %1, %2;" : "=h"(hi) : "f"(f3), "f"(f2));
    return (uint32_t)lo | ((uint32_t)hi << 16);
}

// ---------------------------------------------------------------------------
// Kernel 0 (merged prep, round-10 version): W2 quantize + projections.
// ---------------------------------------------------------------------------
constexpr int W2_BLKS = (IN / 32) * (VPAD / 32);   // 512
constexpr int PENC_BLKS = Bc * Tc / 4;             // 200
constexpr int PDEC_BLKS = Bc * U1 / 4;             // 101
constexpr int PREP_BLKS = W2_BLKS + PENC_BLKS + PDEC_BLKS;  // 813

__global__ __launch_bounds__(256) void prep_kernel(
    const float* __restrict__ W2,
    const float* __restrict__ enc, const float* __restrict__ dec,
    const float* __restrict__ W1, const float* __restrict__ b1) {
    const int blk = blockIdx.x;
    const int tid = threadIdx.x;

    if (blk < W2_BLKS) {
        __shared__ float tile[32][33];
        const int kb = (blk & 15) * 32, vb = (blk >> 4) * 32;
        const int tx = tid & 31, ty = tid >> 5;
#pragma unroll
        for (int i = 0; i < 4; ++i) {
            int k = kb + ty + 8 * i, v = vb + tx;
            tile[ty + 8 * i][tx] = (v < Vc) ? W2[(size_t)k * Vc + v] : 0.f;
        }
        __syncthreads();
        const int v_loc = tid >> 3;
        const int k_loc = (tid & 7) * 4;
        uint32_t pk = pack_e4m3x4(16.f * tile[k_loc + 0][v_loc],
                                  16.f * tile[k_loc + 1][v_loc],
                                  16.f * tile[k_loc + 2][v_loc],
                                  16.f * tile[k_loc + 3][v_loc]);
        *(uint32_t*)(g_W2q + (size_t)(vb + v_loc) * IN + kb + k_loc) = pk;
        return;
    }

    // ---- projection: 4 rows x 512 cols, 2 cols/thread ----
    __shared__ __align__(8) float x_s[4][Hc];
    const int pb = blk - W2_BLKS;
    const bool is_enc = pb < PENC_BLKS;
    const int lb = is_enc ? pb : pb - PENC_BLKS;
    const int r0 = lb * 4;
    const int col = tid * 2;
    const float* __restrict__ X = is_enc ? enc : dec;
    float* __restrict__ Y = is_enc ? g_henc : g_hdec;
    const int woff = is_enc ? 0 : Hc;

    for (int idx = tid; idx < 4 * Hc; idx += 256) {
        int r = idx / Hc, i = idx - r * Hc;
        x_s[r][i] = X[(size_t)(r0 + r) * Hc + i];
    }
    __syncthreads();

    float2 acc[4];
    const float2 bv = is_enc ? *(const float2*)&b1[col] : make_float2(0.f, 0.f);
#pragma unroll
    for (int r = 0; r < 4; ++r) acc[r] = bv;

#pragma unroll 2
    for (int h = 0; h < Hc; h += 2) {
        float2 w0 = *(const float2*)&W1[(size_t)(woff + h) * IN + col];
        float2 w1 = *(const float2*)&W1[(size_t)(woff + h + 1) * IN + col];
#pragma unroll
        for (int r = 0; r < 4; ++r) {
            float2 x = *(const float2*)&x_s[r][h];
            acc[r].x = fmaf(x.x, w0.x, acc[r].x);
            acc[r].y = fmaf(x.x, w0.y, acc[r].y);
            acc[r].x = fmaf(x.y, w1.x, acc[r].x);
            acc[r].y = fmaf(x.y, w1.y, acc[r].y);
        }
    }
#pragma unroll
    for (int r = 0; r < 4; ++r)
        *(float2*)&Y[(size_t)(r0 + r) * IN + col] = acc[r];
}

// ---------------------------------------------------------------------------
// Kernel 1 (dominant): fp8 mma.sync joint GEMM + fused fixed-max logsumexp.
// (byte-identical to the measured 369.2 us baseline)
// ---------------------------------------------------------------------------
__global__ __launch_bounds__(256, 2) void joint_mma(
    const float* __restrict__ b2, const int* __restrict__ tokens) {
    extern __shared__ char dsm[];
    __shared__ __align__(16) float b2s[VPAD];
    __shared__ float cs[4][MT], ctk[4][MT], cbl[MT];

    const int tid = threadIdx.x;
    const int lane = tid & 31, wid = tid >> 5;
    const int warp_m = wid >> 2, warp_n = wid & 3;
    const int qr = lane >> 2, qc = lane & 3;
    const int b = blockIdx.x / BLKS_B;
    const int row0 = (blockIdx.x % BLKS_B) * MT;

    const uint32_t a_base = smemu32(dsm);
    const uint32_t b_base = a_base + A_BYTES;

    // prologue: issue B chunk 0 -> buf 0
    {
#pragma unroll
        for (int q = 0; q < 4; ++q) {
            int i = tid * 4 + q;
            int n = i >> 3, koff = (i & 7) * 16;
            cp_async16(b_base + (uint32_t)(n * BSB + koff),
                       g_W2q + (size_t)n * IN + koff);
        }
        cp_commit();
    }

    for (int i = tid; i < VPAD; i += 256) b2s[i] = (i < Vc) ? b2[i] : -INFINITY;

    // ---- build A tile: fp8(16 * tanh(henc[t] + hdec[u])) ----
    {
        const int rh = tid >> 7;
        const int kt = (tid & 127) * 4;
#pragma unroll 2
        for (int r2 = 0; r2 < MT; r2 += 2) {
            int r = r2 + rh;
            int row = row0 + r;
            uint32_t pk = 0;
            if (row < ROWS_B) {
                int t = row / U1, u = row - t * U1;
                float4 e = *(const float4*)(g_henc + (size_t)(b * Tc + t) * IN + kt);
                float4 d = *(const float4*)(g_hdec + (size_t)(b * U1 + u) * IN + kt);
                pk = pack_e4m3x4(16.f * tanh_approx(e.x + d.x),
                                 16.f * tanh_approx(e.y + d.y),
                                 16.f * tanh_approx(e.z + d.z),
                                 16.f * tanh_approx(e.w + d.w));
            }
            *(uint32_t*)(dsm + r * ASB + kt) = pk;
        }
    }

    float s4[4], tk4[4], bl4[4];
    int rowloc[4], tcol4[4];
#pragma unroll
    for (int s = 0; s < 4; ++s) {
        s4[s] = 0.f; tk4[s] = -INFINITY; bl4[s] = -INFINITY;
        rowloc[s] = warp_m * 32 + (s >> 1) * 16 + (s & 1) * 8 + qr;
        int row = row0 + rowloc[s];
        int u = row % U1;
        tcol4[s] = (row < ROWS_B && u < Uc) ? tokens[b * Uc + u] : -1;
    }

    const int a_row_off = (lane & 7) + ((lane >> 3) & 1) * 8;
    const int a_kb_off = (lane >> 4) * 16;
    const int b_n_off = (lane & 7) + ((lane >> 4) & 1) * 8;
    const int b_kb_off = ((lane >> 3) & 1) * 16;
    const uint32_t a_addr0 =
        a_base + (uint32_t)((warp_m * 32 + a_row_off) * ASB + a_kb_off);
    const uint32_t b_addr0 =
        b_base + (uint32_t)((warp_n * 32 + b_n_off) * BSB + b_kb_off);

    float acc[2][4][4];

    for (int ch = 0; ch < NCHUNK; ++ch) {
        const int buf = ch & 1;
        const int nt = ch >> 2, kc = ch & 3;

        cp_wait0();
        __syncthreads();

        if (ch + 1 < NCHUNK) {
            int nn = (ch + 1) >> 2, nk = (ch + 1) & 3;
            const uint8_t* src = g_W2q + (size_t)(nn * 128) * IN + nk * 128;
            uint32_t dst = b_base + ((ch + 1) & 1) * B_BYTES;
#pragma unroll
            for (int q = 0; q < 4; ++q) {
                int i = tid * 4 + q;
                int n = i >> 3, koff = (i & 7) * 16;
                cp_async16(dst + (uint32_t)(n * BSB + koff),
                           src + (size_t)n * IN + koff);
            }
            cp_commit();
        }

        if (kc == 0) {
#pragma unroll
            for (int mi = 0; mi < 2; ++mi)
#pragma unroll
                for (int nf = 0; nf < 4; ++nf)
#pragma unroll
                    for (int r = 0; r < 4; ++r) acc[mi][nf][r] = 0.f;
        }

        const uint32_t bb = b_addr0 + buf * B_BYTES;
#pragma unroll
        for (int kk = 0; kk < 4; ++kk) {
            uint32_t a[2][4], bfrg[2][4];
#pragma unroll
            for (int mi = 0; mi < 2; ++mi)
                ldmx4(a_addr0 + (uint32_t)(mi * 16 * ASB + kc * 128 + kk * 32),
                      a[mi][0], a[mi][1], a[mi][2], a[mi][3]);
#pragma unroll
            for (int ng = 0; ng < 2; ++ng)
                ldmx4(bb + (uint32_t)(ng * 16 * BSB + kk * 32),
                      bfrg[ng][0], bfrg[ng][1], bfrg[ng][2], bfrg[ng][3]);
#pragma unroll
            for (int mi = 0; mi < 2; ++mi)
#pragma unroll
                for (int nf = 0; nf < 4; ++nf) {
                    int ng = nf >> 1, pr = (nf & 1) * 2;
                    mma_fp8(acc[mi][nf][0], acc[mi][nf][1],
                            acc[mi][nf][2], acc[mi][nf][3],
                            a[mi][0], a[mi][1], a[mi][2], a[mi][3],
                            bfrg[ng][pr], bfrg[ng][pr + 1]);
                }
        }

        if (kc == 3) {
            const int gbase = nt * 128 + warp_n * 32;
#pragma unroll
            for (int s = 0; s < 4; ++s) {
                const int mi = s >> 1, hf = (s & 1) * 2;
                float add = 0.f;
#pragma unroll
                for (int nf = 0; nf < 4; ++nf) {
#pragma unroll
                    for (int j = 0; j < 2; ++j) {
                        int colg = gbase + nf * 8 + qc * 2 + j;
                        float lv = fmaf(acc[mi][nf][hf + j], SCALE_INV, b2s[colg]);
                        add += __expf(lv);
                        if (colg == tcol4[s]) tk4[s] = lv;
                    }
                }
                s4[s] += add;
                if (nt == 0 && warp_n == 0 && qc == 0)
                    bl4[s] = fmaf(acc[mi][0][hf], SCALE_INV, b2s[0]);
            }
        }
    }

#pragma unroll
    for (int off = 1; off <= 2; off <<= 1) {
#pragma unroll
        for (int s = 0; s < 4; ++s) {
            s4[s] += __shfl_xor_sync(0xffffffffu, s4[s], off);
            tk4[s] = fmaxf(tk4[s], __shfl_xor_sync(0xffffffffu, tk4[s], off));
            bl4[s] = fmaxf(bl4[s], __shfl_xor_sync(0xffffffffu, bl4[s], off));
        }
    }
    if (qc == 0) {
#pragma unroll
        for (int s = 0; s < 4; ++s) {
            int r = rowloc[s];
            cs[warp_n][r] = s4[s];
            ctk[warp_n][r] = tk4[s];
            if (warp_n == 0) cbl[r] = bl4[s];
        }
    }
    __syncthreads();

    if (tid < MT) {
        int row = row0 + tid;
        if (row < ROWS_B) {
            float lse = __logf(cs[0][tid] + cs[1][tid] + cs[2][tid] + cs[3][tid]);
            float tk = fmaxf(fmaxf(ctk[0][tid], ctk[1][tid]),
                             fmaxf(ctk[2][tid], ctk[3][tid]));
            int t = row / U1, u = row - t * U1;
            g_blank[(b * Tc + t) * U1 + u] = cbl[tid] - lse;
            if (u < Uc) g_label[(b * Tc + t) * Uc + u] = tk - lse;
        }
    }
}

// ---------------------------------------------------------------------------
// Kernel 2: RNN-T forward DP. Block-wide wavefront (best measured structure),
// but WITHOUT smem staging: blank/label are read directly from global (L2-hot,
// written by joint) with the one-diagonal-ahead prefetch covering L2 latency.
// Removes the staging loop + barrier + 160 KB smem footprint.
// ---------------------------------------------------------------------------
__global__ __launch_bounds__(128) void dp_kernel(
    const int* __restrict__ out_len, const int* __restrict__ tok_len,
    float* __restrict__ out) {
    __shared__ float bufA[U1 + 2], bufB[U1 + 2];
    __shared__ float llk;

    const int b = blockIdx.x, tid = threadIdx.x;
    const float* __restrict__ blankG = g_blank + (size_t)b * Tc * U1;
    const float* __restrict__ labelG = g_label + (size_t)b * Tc * Uc;
    const int tl = out_len[b], ul = tok_len[b];

    float* prev = bufA;
    float* cur = bufB;
    const int u = tid;
    const bool ok = (u <= Uc);

    float cbl = 0.f, clb = 0.f;   // lp values for current diagonal (prefetched)

    for (int d = 0; d <= (Tc - 1) + Uc; ++d) {
        // prefetch lp for diagonal d+1 (independent of the alpha chain)
        float nbl = 0.f, nlb = 0.f;
        {
            int tn = (d + 1) - u;
            if (ok && tn >= 1 && tn < Tc) nbl = __ldg(&blankG[(tn - 1) * U1 + u]);
            if (ok && u >= 1 && tn >= 0 && tn < Tc) nlb = __ldg(&labelG[tn * Uc + (u - 1)]);
        }
        int t = d - u;
        if (ok && t >= 0 && t < Tc) {
            float val;
            if (d == 0) {
                val = 0.f;
            } else {
                float x = (t >= 1) ? prev[u] + cbl : -INFINITY;
                float y = (u >= 1) ? prev[u - 1] + clb : -INFINITY;
                float hi = fmaxf(x, y), lo = fminf(x, y);
                val = (lo == -INFINITY) ? hi : hi + __logf(1.f + __expf(lo - hi));
            }
            cur[u] = val;
            if (t == tl - 1 && u == ul) llk = val;
        }
        __syncthreads();
        float* tmp = prev; prev = cur; cur = tmp;
        cbl = nbl; clb = nlb;
    }

    if (tid == 0) {
        g_ll[b] = llk + __ldg(&blankG[(tl - 1) * U1 + ul]);
        __threadfence();
        int old = atomicAdd(&g_done, 1);
        if (old == Bc - 1) {
            volatile float* ll = g_ll;
            out[0] = -0.25f * (ll[0] + ll[1] + ll[2] + ll[3]);
            g_done = 0;
        }
    }
}

// ---------------------------------------------------------------------------
extern "C" void kernel_launch(void* const* d_in, const int* in_sizes, int n_in,
                              void* d_out, int out_size) {
    const float* enc     = (const float*)d_in[0];
    const float* dec     = (const float*)d_in[1];
    const int*   tokens  = (const int*)d_in[2];
    const int*   out_len = (const int*)d_in[3];
    const int*   tok_len = (const int*)d_in[4];
    const float* W1      = (const float*)d_in[5];
    const float* b1      = (const float*)d_in[6];
    const float* W2      = (const float*)d_in[7];
    const float* b2      = (const float*)d_in[8];
    float* out = (float*)d_out;

    cudaFuncSetAttribute(joint_mma, cudaFuncAttributeMaxDynamicSharedMemorySize, DSMEM);

    prep_kernel<<<PREP_BLKS, 256>>>(W2, enc, dec, W1, b1);
    joint_mma<<<Bc * BLKS_B, 256, DSMEM>>>(b2, tokens);
    dp_kernel<<<Bc, 128>>>(out_len, tok_len, out);
}

// round 14
// speedup vs baseline: 1.0889x; 1.0889x over previous
#include <cuda_runtime.h>
#include <cuda_bf16.h>
#include <math.h>
#include <stdint.h>

#define DEV_INLINE __device__ __forceinline__

// Problem constants
constexpr int Bc = 4, Tc = 200, Uc = 100, U1 = 101, Hc = 320, IN = 512, Vc = 1000;
constexpr int ROWS_B = Tc * U1;                    // 20200 rows (t,u) per batch
constexpr int MT = 64;                             // rows per CTA
constexpr int VPAD = 1024;                         // V padded to 8x128
constexpr int BLKS_B = (ROWS_B + MT - 1) / MT;     // 316

constexpr int ASB = 528;                           // A row stride BYTES (512 + 16)
constexpr int BSB = 144;                           // B row stride BYTES (128 + 16)
constexpr int A_BYTES = MT * ASB;                  // 33792
constexpr int B_BYTES = 128 * BSB;                 // 18432
constexpr int DSMEM = A_BYTES + 2 * B_BYTES;       // 70656
constexpr int NCHUNK = 32;                         // 8 ntiles x 4 kchunks(128 fp8)
constexpr float SCALE_INV = 1.0f / 256.0f;         // (16*h)*(16*w) -> /256

// Scratch (no allocations allowed -> device globals)
__device__ __align__(16) float g_henc[Bc * Tc * IN];
__device__ __align__(16) float g_hdec[Bc * U1 * IN];
__device__ __align__(16) uint8_t g_W2q[VPAD * IN];   // fp8(16*W2^T) [v][k]
__device__ __align__(16) float g_blank[Bc * Tc * U1];
__device__ __align__(16) float g_label[Bc * Tc * Uc];
__device__ float g_ll[Bc];
__device__ int g_done;                               // zero-init; winner resets

// ---------------------------------------------------------------------------
// Helpers
// ---------------------------------------------------------------------------
DEV_INLINE float tanh_approx(float x) {
    float y; asm("tanh.approx.f32 %0, %1;" : "=f"(y) : "f"(x)); return y;
}
DEV_INLINE uint32_t smemu32(const void* p) {
    uint32_t a;
    asm("{ .reg .u64 t; cvta.to.shared.u64 t, %1; cvt.u32.u64 %0, t; }" : "=r"(a) : "l"(p));
    return a;
}
DEV_INLINE void cp_async16(uint32_t dst, const void* src) {
    asm volatile("cp.async.ca.shared.global [%0], [%1], 16;"
                 :: "r"(dst), "l"(src) : "memory");
}
DEV_INLINE void cp_commit() { asm volatile("cp.async.commit_group;" ::: "memory"); }
DEV_INLINE void cp_wait0()  { asm volatile("cp.async.wait_group 0;" ::: "memory"); }

DEV_INLINE void ldmx4(uint32_t addr, uint32_t& r0, uint32_t& r1, uint32_t& r2, uint32_t& r3) {
    asm volatile("ldmatrix.sync.aligned.m8n8.x4.shared.b16 {%0,%1,%2,%3}, [%4];"
                 : "=r"(r0), "=r"(r1), "=r"(r2), "=r"(r3) : "r"(addr));
}
DEV_INLINE void mma_fp8(float& c0, float& c1, float& c2, float& c3,
                        uint32_t a0, uint32_t a1, uint32_t a2, uint32_t a3,
                        uint32_t b0, uint32_t b1) {
    asm volatile(
        "mma.sync.aligned.m16n8k32.row.col.f32.e4m3.e4m3.f32 "
        "{%0,%1,%2,%3}, {%4,%5,%6,%7}, {%8,%9}, {%0,%1,%2,%3};"
        : "+f"(c0), "+f"(c1), "+f"(c2), "+f"(c3)
        : "r"(a0), "r"(a1), "r"(a2), "r"(a3), "r"(b0), "r"(b1));
}
DEV_INLINE uint32_t pack_e4m3x4(float f0, float f1, float f2, float f3) {
    uint16_t lo, hi;
    asm("cvt.rn.satfinite.e4m3x2.f32 %0, %1, %2;" : "=h"(lo) : "f"(f1), "f"(f0));
    asm("cvt.rn.satfinite.e4m3x2.f32 %0, %1, %2;" : "=h"(hi) : "f"(f3), "f"(f2));
    return (uint32_t)lo | ((uint32_t)hi << 16);
}

// ---------------------------------------------------------------------------
// Kernel 0 (merged prep): W2 transpose/quantize + both projections.
//   blocks [0, W2_BLKS)      : W2 [512][1000] f32 -> fp8(16*w) [1024][512]
//   blocks [W2_BLKS, ...)    : projections, 4 rows x 512 cols per block,
//     256 threads x 2 cols (float2 W1 loads), h unrolled x2 (float2 LDS).
// ---------------------------------------------------------------------------
constexpr int W2_BLKS = (IN / 32) * (VPAD / 32);   // 512
constexpr int PENC_BLKS = Bc * Tc / 4;             // 200
constexpr int PDEC_BLKS = Bc * U1 / 4;             // 101
constexpr int PREP_BLKS = W2_BLKS + PENC_BLKS + PDEC_BLKS;  // 813

__global__ __launch_bounds__(256) void prep_kernel(
    const float* __restrict__ W2,
    const float* __restrict__ enc, const float* __restrict__ dec,
    const float* __restrict__ W1, const float* __restrict__ b1) {
    const int blk = blockIdx.x;
    const int tid = threadIdx.x;

    if (blk < W2_BLKS) {
        __shared__ float tile[32][33];
        const int kb = (blk & 15) * 32, vb = (blk >> 4) * 32;
        const int tx = tid & 31, ty = tid >> 5;
#pragma unroll
        for (int i = 0; i < 4; ++i) {
            int k = kb + ty + 8 * i, v = vb + tx;
            tile[ty + 8 * i][tx] = (v < Vc) ? W2[(size_t)k * Vc + v] : 0.f;
        }
        __syncthreads();
        const int v_loc = tid >> 3;
        const int k_loc = (tid & 7) * 4;
        uint32_t pk = pack_e4m3x4(16.f * tile[k_loc + 0][v_loc],
                                  16.f * tile[k_loc + 1][v_loc],
                                  16.f * tile[k_loc + 2][v_loc],
                                  16.f * tile[k_loc + 3][v_loc]);
        *(uint32_t*)(g_W2q + (size_t)(vb + v_loc) * IN + kb + k_loc) = pk;
        return;
    }

    // ---- projection: 4 rows x 512 cols, 2 cols/thread ----
    __shared__ __align__(8) float x_s[4][Hc];
    const int pb = blk - W2_BLKS;
    const bool is_enc = pb < PENC_BLKS;
    const int lb = is_enc ? pb : pb - PENC_BLKS;
    const int r0 = lb * 4;
    const int col = tid * 2;
    const float* __restrict__ X = is_enc ? enc : dec;
    float* __restrict__ Y = is_enc ? g_henc : g_hdec;
    const int woff = is_enc ? 0 : Hc;

    for (int idx = tid; idx < 4 * Hc; idx += 256) {
        int r = idx / Hc, i = idx - r * Hc;
        x_s[r][i] = X[(size_t)(r0 + r) * Hc + i];
    }
    __syncthreads();

    float2 acc[4];
    const float2 bv = is_enc ? *(const float2*)&b1[col] : make_float2(0.f, 0.f);
#pragma unroll
    for (int r = 0; r < 4; ++r) acc[r] = bv;

#pragma unroll 2
    for (int h = 0; h < Hc; h += 2) {
        float2 w0 = *(const float2*)&W1[(size_t)(woff + h) * IN + col];
        float2 w1 = *(const float2*)&W1[(size_t)(woff + h + 1) * IN + col];
#pragma unroll
        for (int r = 0; r < 4; ++r) {
            float2 x = *(const float2*)&x_s[r][h];
            acc[r].x = fmaf(x.x, w0.x, acc[r].x);
            acc[r].y = fmaf(x.x, w0.y, acc[r].y);
            acc[r].x = fmaf(x.y, w1.x, acc[r].x);
            acc[r].y = fmaf(x.y, w1.y, acc[r].y);
        }
    }
#pragma unroll
    for (int r = 0; r < 4; ++r)
        *(float2*)&Y[(size_t)(r0 + r) * IN + col] = acc[r];
}

// ---------------------------------------------------------------------------
// Kernel 1 (dominant): fp8 mma.sync joint GEMM + fused fixed-max logsumexp.
//   A = fp8(16*tanh(henc+hdec)) [64 x 512] (row stride 528 B)
//   B = fp8(16*W2t) chunks [128 n x 128 k], cp.async double-buffered, 1-ahead
//   acc = 256 * logits (fp32); epilogue: lv = acc/256 + b2.
// 256 threads = 8 warps = 2(m) x 4(n); warp tile 32 x 32.
// ---------------------------------------------------------------------------
__global__ __launch_bounds__(256, 2) void joint_mma(
    const float* __restrict__ b2, const int* __restrict__ tokens) {
    extern __shared__ char dsm[];
    __shared__ __align__(16) float b2s[VPAD];
    __shared__ float cs[4][MT], ctk[4][MT], cbl[MT];

    const int tid = threadIdx.x;
    const int lane = tid & 31, wid = tid >> 5;
    const int warp_m = wid >> 2, warp_n = wid & 3;
    const int qr = lane >> 2, qc = lane & 3;
    const int b = blockIdx.x / BLKS_B;
    const int row0 = (blockIdx.x % BLKS_B) * MT;

    const uint32_t a_base = smemu32(dsm);
    const uint32_t b_base = a_base + A_BYTES;

    // prologue: issue B chunk 0 -> buf 0
    {
#pragma unroll
        for (int q = 0; q < 4; ++q) {
            int i = tid * 4 + q;
            int n = i >> 3, koff = (i & 7) * 16;
            cp_async16(b_base + (uint32_t)(n * BSB + koff),
                       g_W2q + (size_t)n * IN + koff);
        }
        cp_commit();
    }

    for (int i = tid; i < VPAD; i += 256) b2s[i] = (i < Vc) ? b2[i] : -INFINITY;

    // ---- build A tile: fp8(16 * tanh(henc[t] + hdec[u])) ----
    {
        const int rh = tid >> 7;
        const int kt = (tid & 127) * 4;
#pragma unroll 2
        for (int r2 = 0; r2 < MT; r2 += 2) {
            int r = r2 + rh;
            int row = row0 + r;
            uint32_t pk = 0;
            if (row < ROWS_B) {
                int t = row / U1, u = row - t * U1;
                float4 e = *(const float4*)(g_henc + (size_t)(b * Tc + t) * IN + kt);
                float4 d = *(const float4*)(g_hdec + (size_t)(b * U1 + u) * IN + kt);
                pk = pack_e4m3x4(16.f * tanh_approx(e.x + d.x),
                                 16.f * tanh_approx(e.y + d.y),
                                 16.f * tanh_approx(e.z + d.z),
                                 16.f * tanh_approx(e.w + d.w));
            }
            *(uint32_t*)(dsm + r * ASB + kt) = pk;
        }
    }

    float s4[4], tk4[4], bl4[4];
    int rowloc[4], tcol4[4];
#pragma unroll
    for (int s = 0; s < 4; ++s) {
        s4[s] = 0.f; tk4[s] = -INFINITY; bl4[s] = -INFINITY;
        rowloc[s] = warp_m * 32 + (s >> 1) * 16 + (s & 1) * 8 + qr;
        int row = row0 + rowloc[s];
        int u = row % U1;
        tcol4[s] = (row < ROWS_B && u < Uc) ? tokens[b * Uc + u] : -1;
    }

    const int a_row_off = (lane & 7) + ((lane >> 3) & 1) * 8;
    const int a_kb_off = (lane >> 4) * 16;
    const int b_n_off = (lane & 7) + ((lane >> 4) & 1) * 8;
    const int b_kb_off = ((lane >> 3) & 1) * 16;
    const uint32_t a_addr0 =
        a_base + (uint32_t)((warp_m * 32 + a_row_off) * ASB + a_kb_off);
    const uint32_t b_addr0 =
        b_base + (uint32_t)((warp_n * 32 + b_n_off) * BSB + b_kb_off);

    float acc[2][4][4];

    for (int ch = 0; ch < NCHUNK; ++ch) {
        const int buf = ch & 1;
        const int nt = ch >> 2, kc = ch & 3;

        cp_wait0();
        __syncthreads();

        if (ch + 1 < NCHUNK) {
            int nn = (ch + 1) >> 2, nk = (ch + 1) & 3;
            const uint8_t* src = g_W2q + (size_t)(nn * 128) * IN + nk * 128;
            uint32_t dst = b_base + ((ch + 1) & 1) * B_BYTES;
#pragma unroll
            for (int q = 0; q < 4; ++q) {
                int i = tid * 4 + q;
                int n = i >> 3, koff = (i & 7) * 16;
                cp_async16(dst + (uint32_t)(n * BSB + koff),
                           src + (size_t)n * IN + koff);
            }
            cp_commit();
        }

        if (kc == 0) {
#pragma unroll
            for (int mi = 0; mi < 2; ++mi)
#pragma unroll
                for (int nf = 0; nf < 4; ++nf)
#pragma unroll
                    for (int r = 0; r < 4; ++r) acc[mi][nf][r] = 0.f;
        }

        const uint32_t bb = b_addr0 + buf * B_BYTES;
#pragma unroll
        for (int kk = 0; kk < 4; ++kk) {
            uint32_t a[2][4], bfrg[2][4];
#pragma unroll
            for (int mi = 0; mi < 2; ++mi)
                ldmx4(a_addr0 + (uint32_t)(mi * 16 * ASB + kc * 128 + kk * 32),
                      a[mi][0], a[mi][1], a[mi][2], a[mi][3]);
#pragma unroll
            for (int ng = 0; ng < 2; ++ng)
                ldmx4(bb + (uint32_t)(ng * 16 * BSB + kk * 32),
                      bfrg[ng][0], bfrg[ng][1], bfrg[ng][2], bfrg[ng][3]);
#pragma unroll
            for (int mi = 0; mi < 2; ++mi)
#pragma unroll
                for (int nf = 0; nf < 4; ++nf) {
                    int ng = nf >> 1, pr = (nf & 1) * 2;
                    mma_fp8(acc[mi][nf][0], acc[mi][nf][1],
                            acc[mi][nf][2], acc[mi][nf][3],
                            a[mi][0], a[mi][1], a[mi][2], a[mi][3],
                            bfrg[ng][pr], bfrg[ng][pr + 1]);
                }
        }

        if (kc == 3) {
            const int gbase = nt * 128 + warp_n * 32;
#pragma unroll
            for (int s = 0; s < 4; ++s) {
                const int mi = s >> 1, hf = (s & 1) * 2;
                float add = 0.f;
#pragma unroll
                for (int nf = 0; nf < 4; ++nf) {
#pragma unroll
                    for (int j = 0; j < 2; ++j) {
                        int colg = gbase + nf * 8 + qc * 2 + j;
                        float lv = fmaf(acc[mi][nf][hf + j], SCALE_INV, b2s[colg]);
                        add += __expf(lv);
                        if (colg == tcol4[s]) tk4[s] = lv;
                    }
                }
                s4[s] += add;
                if (nt == 0 && warp_n == 0 && qc == 0)
                    bl4[s] = fmaf(acc[mi][0][hf], SCALE_INV, b2s[0]);
            }
        }
    }

#pragma unroll
    for (int off = 1; off <= 2; off <<= 1) {
#pragma unroll
        for (int s = 0; s < 4; ++s) {
            s4[s] += __shfl_xor_sync(0xffffffffu, s4[s], off);
            tk4[s] = fmaxf(tk4[s], __shfl_xor_sync(0xffffffffu, tk4[s], off));
            bl4[s] = fmaxf(bl4[s], __shfl_xor_sync(0xffffffffu, bl4[s], off));
        }
    }
    if (qc == 0) {
#pragma unroll
        for (int s = 0; s < 4; ++s) {
            int r = rowloc[s];
            cs[warp_n][r] = s4[s];
            ctk[warp_n][r] = tk4[s];
            if (warp_n == 0) cbl[r] = bl4[s];
        }
    }
    __syncthreads();

    if (tid < MT) {
        int row = row0 + tid;
        if (row < ROWS_B) {
            float lse = __logf(cs[0][tid] + cs[1][tid] + cs[2][tid] + cs[3][tid]);
            float tk = fmaxf(fmaxf(ctk[0][tid], ctk[1][tid]),
                             fmaxf(ctk[2][tid], ctk[3][tid]));
            int t = row / U1, u = row - t * U1;
            g_blank[(b * Tc + t) * U1 + u] = cbl[tid] - lse;
            if (u < Uc) g_label[(b * Tc + t) * Uc + u] = tk - lse;
        }
    }
}

// ---------------------------------------------------------------------------
// Kernel 2: RNN-T forward DP. Block-wide wavefront with smem-staged lp and
// one-diagonal-ahead prefetch (best measured of five variants). Last block
// writes the final output (finalize folded in).
// ---------------------------------------------------------------------------
constexpr int DP_SMEM = (Tc * U1 + Tc * Uc) * (int)sizeof(float); // 160800

__global__ __launch_bounds__(128) void dp_kernel(
    const int* __restrict__ out_len, const int* __restrict__ tok_len,
    float* __restrict__ out) {
    extern __shared__ float lp[];
    float* blankS = lp;
    float* labelS = lp + Tc * U1;
    __shared__ float llk;

    const int b = blockIdx.x, tid = threadIdx.x;
    {
        const float4* src = (const float4*)(g_blank + (size_t)b * Tc * U1);
        float4* dst = (float4*)blankS;
        for (int i = tid; i < Tc * U1 / 4; i += 128) dst[i] = src[i];
        const float4* src2 = (const float4*)(g_label + (size_t)b * Tc * Uc);
        float4* dst2 = (float4*)labelS;
        for (int i = tid; i < Tc * Uc / 4; i += 128) dst2[i] = src2[i];
    }
    const int tl = out_len[b], ul = tok_len[b];
    __syncthreads();

    __shared__ float bufA[U1 + 2], bufB[U1 + 2];
    float* prev = bufA;
    float* cur = bufB;
    const int u = tid;
    const bool ok = (u <= Uc);

    float cbl = 0.f, clb = 0.f;

    for (int d = 0; d <= (Tc - 1) + Uc; ++d) {
        float nbl = 0.f, nlb = 0.f;
        {
            int tn = (d + 1) - u;
            if (ok && tn >= 1 && tn < Tc) nbl = blankS[(tn - 1) * U1 + u];
            if (ok && u >= 1 && tn >= 0 && tn < Tc) nlb = labelS[tn * Uc + (u - 1)];
        }
        int t = d - u;
        if (ok && t >= 0 && t < Tc) {
            float val;
            if (d == 0) {
                val = 0.f;
            } else {
                float x = (t >= 1) ? prev[u] + cbl : -INFINITY;
                float y = (u >= 1) ? prev[u - 1] + clb : -INFINITY;
                float hi = fmaxf(x, y), lo = fminf(x, y);
                val = (lo == -INFINITY) ? hi : hi + __logf(1.f + __expf(lo - hi));
            }
            cur[u] = val;
            if (t == tl - 1 && u == ul) llk = val;
        }
        __syncthreads();
        float* tmp = prev; prev = cur; cur = tmp;
        cbl = nbl; clb = nlb;
    }

    if (tid == 0) {
        g_ll[b] = llk + blankS[(tl - 1) * U1 + ul];
        __threadfence();
        int old = atomicAdd(&g_done, 1);
        if (old == Bc - 1) {
            volatile float* ll = g_ll;
            out[0] = -0.25f * (ll[0] + ll[1] + ll[2] + ll[3]);
            g_done = 0;
        }
    }
}

// ---------------------------------------------------------------------------
extern "C" void kernel_launch(void* const* d_in, const int* in_sizes, int n_in,
                              void* d_out, int out_size) {
    const float* enc     = (const float*)d_in[0];
    const float* dec     = (const float*)d_in[1];
    const int*   tokens  = (const int*)d_in[2];
    const int*   out_len = (const int*)d_in[3];
    const int*   tok_len = (const int*)d_in[4];
    const float* W1      = (const float*)d_in[5];
    const float* b1      = (const float*)d_in[6];
    const float* W2      = (const float*)d_in[7];
    const float* b2      = (const float*)d_in[8];
    float* out = (float*)d_out;

    cudaFuncSetAttribute(joint_mma, cudaFuncAttributeMaxDynamicSharedMemorySize, DSMEM);
    cudaFuncSetAttribute(dp_kernel, cudaFuncAttributeMaxDynamicSharedMemorySize, DP_SMEM);

    prep_kernel<<<PREP_BLKS, 256>>>(W2, enc, dec, W1, b1);
    joint_mma<<<Bc * BLKS_B, 256, DSMEM>>>(b2, tokens);
    dp_kernel<<<Bc, 128, DP_SMEM>>>(out_len, tok_len, out);
}

// round 15
// speedup vs baseline: 1.1202x; 1.0287x over previous
#include <cuda_runtime.h>
#include <cuda_bf16.h>
#include <math.h>
#include <stdint.h>

#define DEV_INLINE __device__ __forceinline__

// Problem constants
constexpr int Bc = 4, Tc = 200, Uc = 100, U1 = 101, Hc = 320, IN = 512, Vc = 1000;
constexpr int ROWS_B = Tc * U1;                    // 20200 rows (t,u) per batch
constexpr int MT = 96;                             // rows per CTA (3-wave tiling)
constexpr int VPAD = 1024;                         // V padded to 8x128
constexpr int BLKS_B = (ROWS_B + MT - 1) / MT;     // 211

constexpr int ASB = 528;                           // A row stride BYTES (512 + 16)
constexpr int BSB = 144;                           // B row stride BYTES (128 + 16)
constexpr int A_BYTES = MT * ASB;                  // 50688
constexpr int B_BYTES = 128 * BSB;                 // 18432
constexpr int DSMEM = A_BYTES + 2 * B_BYTES;       // 87552 -> 2 CTAs/SM
constexpr int NCHUNK = 32;                         // 8 ntiles x 4 kchunks(128 fp8)
constexpr float SCALE_INV = 1.0f / 256.0f;         // (16*h)*(16*w) -> /256

// Scratch (no allocations allowed -> device globals)
__device__ __align__(16) float g_henc[Bc * Tc * IN];
__device__ __align__(16) float g_hdec[Bc * U1 * IN];
__device__ __align__(16) uint8_t g_W2q[VPAD * IN];   // fp8(16*W2^T) [v][k]
__device__ __align__(16) float g_blank[Bc * Tc * U1];
__device__ __align__(16) float g_label[Bc * Tc * Uc];
__device__ float g_ll[Bc];
__device__ int g_done;                               // zero-init; winner resets

// ---------------------------------------------------------------------------
// Helpers
// ---------------------------------------------------------------------------
DEV_INLINE float tanh_approx(float x) {
    float y; asm("tanh.approx.f32 %0, %1;" : "=f"(y) : "f"(x)); return y;
}
DEV_INLINE uint32_t smemu32(const void* p) {
    uint32_t a;
    asm("{ .reg .u64 t; cvta.to.shared.u64 t, %1; cvt.u32.u64 %0, t; }" : "=r"(a) : "l"(p));
    return a;
}
DEV_INLINE void cp_async16(uint32_t dst, const void* src) {
    asm volatile("cp.async.ca.shared.global [%0], [%1], 16;"
                 :: "r"(dst), "l"(src) : "memory");
}
DEV_INLINE void cp_commit() { asm volatile("cp.async.commit_group;" ::: "memory"); }
DEV_INLINE void cp_wait0()  { asm volatile("cp.async.wait_group 0;" ::: "memory"); }

DEV_INLINE void ldmx4(uint32_t addr, uint32_t& r0, uint32_t& r1, uint32_t& r2, uint32_t& r3) {
    asm volatile("ldmatrix.sync.aligned.m8n8.x4.shared.b16 {%0,%1,%2,%3}, [%4];"
                 : "=r"(r0), "=r"(r1), "=r"(r2), "=r"(r3) : "r"(addr));
}
DEV_INLINE void mma_fp8(float& c0, float& c1, float& c2, float& c3,
                        uint32_t a0, uint32_t a1, uint32_t a2, uint32_t a3,
                        uint32_t b0, uint32_t b1) {
    asm volatile(
        "mma.sync.aligned.m16n8k32.row.col.f32.e4m3.e4m3.f32 "
        "{%0,%1,%2,%3}, {%4,%5,%6,%7}, {%8,%9}, {%0,%1,%2,%3};"
        : "+f"(c0), "+f"(c1), "+f"(c2), "+f"(c3)
        : "r"(a0), "r"(a1), "r"(a2), "r"(a3), "r"(b0), "r"(b1));
}
DEV_INLINE uint32_t pack_e4m3x4(float f0, float f1, float f2, float f3) {
    uint16_t lo, hi;
    asm("cvt.rn.satfinite.e4m3x2.f32 %0, %1, %2;" : "=h"(lo) : "f"(f1), "f"(f0));
    asm("cvt.rn.satfinite.e4m3x2.f32 %0, %1, %2;" : "=h"(hi) : "f"(f3), "f"(f2));
    return (uint32_t)lo | ((uint32_t)hi << 16);
}

// ---------------------------------------------------------------------------
// Kernel 0 (merged prep): W2 transpose/quantize + both projections.
// (byte-identical to the 368.8 us baseline)
// ---------------------------------------------------------------------------
constexpr int W2_BLKS = (IN / 32) * (VPAD / 32);   // 512
constexpr int PENC_BLKS = Bc * Tc / 4;             // 200
constexpr int PDEC_BLKS = Bc * U1 / 4;             // 101
constexpr int PREP_BLKS = W2_BLKS + PENC_BLKS + PDEC_BLKS;  // 813

__global__ __launch_bounds__(256) void prep_kernel(
    const float* __restrict__ W2,
    const float* __restrict__ enc, const float* __restrict__ dec,
    const float* __restrict__ W1, const float* __restrict__ b1) {
    const int blk = blockIdx.x;
    const int tid = threadIdx.x;

    if (blk < W2_BLKS) {
        __shared__ float tile[32][33];
        const int kb = (blk & 15) * 32, vb = (blk >> 4) * 32;
        const int tx = tid & 31, ty = tid >> 5;
#pragma unroll
        for (int i = 0; i < 4; ++i) {
            int k = kb + ty + 8 * i, v = vb + tx;
            tile[ty + 8 * i][tx] = (v < Vc) ? W2[(size_t)k * Vc + v] : 0.f;
        }
        __syncthreads();
        const int v_loc = tid >> 3;
        const int k_loc = (tid & 7) * 4;
        uint32_t pk = pack_e4m3x4(16.f * tile[k_loc + 0][v_loc],
                                  16.f * tile[k_loc + 1][v_loc],
                                  16.f * tile[k_loc + 2][v_loc],
                                  16.f * tile[k_loc + 3][v_loc]);
        *(uint32_t*)(g_W2q + (size_t)(vb + v_loc) * IN + kb + k_loc) = pk;
        return;
    }

    // ---- projection: 4 rows x 512 cols, 2 cols/thread ----
    __shared__ __align__(8) float x_s[4][Hc];
    const int pb = blk - W2_BLKS;
    const bool is_enc = pb < PENC_BLKS;
    const int lb = is_enc ? pb : pb - PENC_BLKS;
    const int r0 = lb * 4;
    const int col = tid * 2;
    const float* __restrict__ X = is_enc ? enc : dec;
    float* __restrict__ Y = is_enc ? g_henc : g_hdec;
    const int woff = is_enc ? 0 : Hc;

    for (int idx = tid; idx < 4 * Hc; idx += 256) {
        int r = idx / Hc, i = idx - r * Hc;
        x_s[r][i] = X[(size_t)(r0 + r) * Hc + i];
    }
    __syncthreads();

    float2 acc[4];
    const float2 bv = is_enc ? *(const float2*)&b1[col] : make_float2(0.f, 0.f);
#pragma unroll
    for (int r = 0; r < 4; ++r) acc[r] = bv;

#pragma unroll 2
    for (int h = 0; h < Hc; h += 2) {
        float2 w0 = *(const float2*)&W1[(size_t)(woff + h) * IN + col];
        float2 w1 = *(const float2*)&W1[(size_t)(woff + h + 1) * IN + col];
#pragma unroll
        for (int r = 0; r < 4; ++r) {
            float2 x = *(const float2*)&x_s[r][h];
            acc[r].x = fmaf(x.x, w0.x, acc[r].x);
            acc[r].y = fmaf(x.x, w0.y, acc[r].y);
            acc[r].x = fmaf(x.y, w1.x, acc[r].x);
            acc[r].y = fmaf(x.y, w1.y, acc[r].y);
        }
    }
#pragma unroll
    for (int r = 0; r < 4; ++r)
        *(float2*)&Y[(size_t)(r0 + r) * IN + col] = acc[r];
}

// ---------------------------------------------------------------------------
// Kernel 1 (dominant): fp8 mma.sync joint GEMM + fused fixed-max logsumexp.
//   MT=96 rows/CTA -> 844 CTAs = 2.85 waves at 2 CTA/SM (was 4.27): cuts the
//   last-wave quantization tail from ~27%-full to ~85%-full.
//   Warp tile 48(m) x 32(n): acc[3][4][4] = 48 regs, all indexing static.
// ---------------------------------------------------------------------------
__global__ __launch_bounds__(256, 2) void joint_mma(
    const float* __restrict__ b2, const int* __restrict__ tokens) {
    extern __shared__ char dsm[];
    __shared__ __align__(16) float b2s[VPAD];
    __shared__ float cs[4][MT], ctk[4][MT], cbl[MT];

    const int tid = threadIdx.x;
    const int lane = tid & 31, wid = tid >> 5;
    const int warp_m = wid >> 2, warp_n = wid & 3;
    const int qr = lane >> 2, qc = lane & 3;
    const int b = blockIdx.x / BLKS_B;
    const int row0 = (blockIdx.x % BLKS_B) * MT;

    const uint32_t a_base = smemu32(dsm);
    const uint32_t b_base = a_base + A_BYTES;

    // prologue: issue B chunk 0 -> buf 0
    {
#pragma unroll
        for (int q = 0; q < 4; ++q) {
            int i = tid * 4 + q;
            int n = i >> 3, koff = (i & 7) * 16;
            cp_async16(b_base + (uint32_t)(n * BSB + koff),
                       g_W2q + (size_t)n * IN + koff);
        }
        cp_commit();
    }

    for (int i = tid; i < VPAD; i += 256) b2s[i] = (i < Vc) ? b2[i] : -INFINITY;

    // ---- build A tile: fp8(16 * tanh(henc[t] + hdec[u])), 96 rows ----
    {
        const int rh = tid >> 7;
        const int kt = (tid & 127) * 4;
#pragma unroll 2
        for (int r2 = 0; r2 < MT; r2 += 2) {
            int r = r2 + rh;
            int row = row0 + r;
            uint32_t pk = 0;
            if (row < ROWS_B) {
                int t = row / U1, u = row - t * U1;
                float4 e = *(const float4*)(g_henc + (size_t)(b * Tc + t) * IN + kt);
                float4 d = *(const float4*)(g_hdec + (size_t)(b * U1 + u) * IN + kt);
                pk = pack_e4m3x4(16.f * tanh_approx(e.x + d.x),
                                 16.f * tanh_approx(e.y + d.y),
                                 16.f * tanh_approx(e.z + d.z),
                                 16.f * tanh_approx(e.w + d.w));
            }
            *(uint32_t*)(dsm + r * ASB + kt) = pk;
        }
    }

    // per-slot (6 rows/thread) state; slot s = mi*2+half:
    //   row = warp_m*48 + mi*16 + half*8 + qr
    float s4[6], tk4[6], bl4[6];
    int rowloc[6], tcol4[6];
#pragma unroll
    for (int s = 0; s < 6; ++s) {
        s4[s] = 0.f; tk4[s] = -INFINITY; bl4[s] = -INFINITY;
        rowloc[s] = warp_m * 48 + (s >> 1) * 16 + (s & 1) * 8 + qr;
        int row = row0 + rowloc[s];
        int u = row % U1;
        tcol4[s] = (row < ROWS_B && u < Uc) ? tokens[b * Uc + u] : -1;
    }

    const int a_row_off = (lane & 7) + ((lane >> 3) & 1) * 8;
    const int a_kb_off = (lane >> 4) * 16;
    const int b_n_off = (lane & 7) + ((lane >> 4) & 1) * 8;
    const int b_kb_off = ((lane >> 3) & 1) * 16;
    const uint32_t a_addr0 =
        a_base + (uint32_t)((warp_m * 48 + a_row_off) * ASB + a_kb_off);
    const uint32_t b_addr0 =
        b_base + (uint32_t)((warp_n * 32 + b_n_off) * BSB + b_kb_off);

    float acc[3][4][4];   // [mi][nf][frag] -> 48 regs

    for (int ch = 0; ch < NCHUNK; ++ch) {
        const int buf = ch & 1;
        const int nt = ch >> 2, kc = ch & 3;

        cp_wait0();
        __syncthreads();

        if (ch + 1 < NCHUNK) {
            int nn = (ch + 1) >> 2, nk = (ch + 1) & 3;
            const uint8_t* src = g_W2q + (size_t)(nn * 128) * IN + nk * 128;
            uint32_t dst = b_base + ((ch + 1) & 1) * B_BYTES;
#pragma unroll
            for (int q = 0; q < 4; ++q) {
                int i = tid * 4 + q;
                int n = i >> 3, koff = (i & 7) * 16;
                cp_async16(dst + (uint32_t)(n * BSB + koff),
                           src + (size_t)n * IN + koff);
            }
            cp_commit();
        }

        if (kc == 0) {
#pragma unroll
            for (int mi = 0; mi < 3; ++mi)
#pragma unroll
                for (int nf = 0; nf < 4; ++nf)
#pragma unroll
                    for (int r = 0; r < 4; ++r) acc[mi][nf][r] = 0.f;
        }

        const uint32_t bb = b_addr0 + buf * B_BYTES;
#pragma unroll
        for (int kk = 0; kk < 4; ++kk) {
            uint32_t a[3][4], bfrg[2][4];
#pragma unroll
            for (int mi = 0; mi < 3; ++mi)
                ldmx4(a_addr0 + (uint32_t)(mi * 16 * ASB + kc * 128 + kk * 32),
                      a[mi][0], a[mi][1], a[mi][2], a[mi][3]);
#pragma unroll
            for (int ng = 0; ng < 2; ++ng)
                ldmx4(bb + (uint32_t)(ng * 16 * BSB + kk * 32),
                      bfrg[ng][0], bfrg[ng][1], bfrg[ng][2], bfrg[ng][3]);
#pragma unroll
            for (int mi = 0; mi < 3; ++mi)
#pragma unroll
                for (int nf = 0; nf < 4; ++nf) {
                    int ng = nf >> 1, pr = (nf & 1) * 2;
                    mma_fp8(acc[mi][nf][0], acc[mi][nf][1],
                            acc[mi][nf][2], acc[mi][nf][3],
                            a[mi][0], a[mi][1], a[mi][2], a[mi][3],
                            bfrg[ng][pr], bfrg[ng][pr + 1]);
                }
        }

        if (kc == 3) {
            const int gbase = nt * 128 + warp_n * 32;
#pragma unroll
            for (int s = 0; s < 6; ++s) {
                const int mi = s >> 1, hf = (s & 1) * 2;
                float add = 0.f;
#pragma unroll
                for (int nf = 0; nf < 4; ++nf) {
#pragma unroll
                    for (int j = 0; j < 2; ++j) {
                        int colg = gbase + nf * 8 + qc * 2 + j;
                        float lv = fmaf(acc[mi][nf][hf + j], SCALE_INV, b2s[colg]);
                        add += __expf(lv);
                        if (colg == tcol4[s]) tk4[s] = lv;
                    }
                }
                s4[s] += add;
                if (nt == 0 && warp_n == 0 && qc == 0)
                    bl4[s] = fmaf(acc[mi][0][hf], SCALE_INV, b2s[0]);
            }
        }
    }

#pragma unroll
    for (int off = 1; off <= 2; off <<= 1) {
#pragma unroll
        for (int s = 0; s < 6; ++s) {
            s4[s] += __shfl_xor_sync(0xffffffffu, s4[s], off);
            tk4[s] = fmaxf(tk4[s], __shfl_xor_sync(0xffffffffu, tk4[s], off));
            bl4[s] = fmaxf(bl4[s], __shfl_xor_sync(0xffffffffu, bl4[s], off));
        }
    }
    if (qc == 0) {
#pragma unroll
        for (int s = 0; s < 6; ++s) {
            int r = rowloc[s];
            cs[warp_n][r] = s4[s];
            ctk[warp_n][r] = tk4[s];
            if (warp_n == 0) cbl[r] = bl4[s];
        }
    }
    __syncthreads();

    if (tid < MT) {
        int row = row0 + tid;
        if (row < ROWS_B) {
            float lse = __logf(cs[0][tid] + cs[1][tid] + cs[2][tid] + cs[3][tid]);
            float tk = fmaxf(fmaxf(ctk[0][tid], ctk[1][tid]),
                             fmaxf(ctk[2][tid], ctk[3][tid]));
            int t = row / U1, u = row - t * U1;
            g_blank[(b * Tc + t) * U1 + u] = cbl[tid] - lse;
            if (u < Uc) g_label[(b * Tc + t) * Uc + u] = tk - lse;
        }
    }
}

// ---------------------------------------------------------------------------
// Kernel 2: RNN-T forward DP (byte-identical to the 368.8 us baseline).
// ---------------------------------------------------------------------------
constexpr int DP_SMEM = (Tc * U1 + Tc * Uc) * (int)sizeof(float); // 160800

__global__ __launch_bounds__(128) void dp_kernel(
    const int* __restrict__ out_len, const int* __restrict__ tok_len,
    float* __restrict__ out) {
    extern __shared__ float lp[];
    float* blankS = lp;
    float* labelS = lp + Tc * U1;
    __shared__ float llk;

    const int b = blockIdx.x, tid = threadIdx.x;
    {
        const float4* src = (const float4*)(g_blank + (size_t)b * Tc * U1);
        float4* dst = (float4*)blankS;
        for (int i = tid; i < Tc * U1 / 4; i += 128) dst[i] = src[i];
        const float4* src2 = (const float4*)(g_label + (size_t)b * Tc * Uc);
        float4* dst2 = (float4*)labelS;
        for (int i = tid; i < Tc * Uc / 4; i += 128) dst2[i] = src2[i];
    }
    const int tl = out_len[b], ul = tok_len[b];
    __syncthreads();

    __shared__ float bufA[U1 + 2], bufB[U1 + 2];
    float* prev = bufA;
    float* cur = bufB;
    const int u = tid;
    const bool ok = (u <= Uc);

    float cbl = 0.f, clb = 0.f;

    for (int d = 0; d <= (Tc - 1) + Uc; ++d) {
        float nbl = 0.f, nlb = 0.f;
        {
            int tn = (d + 1) - u;
            if (ok && tn >= 1 && tn < Tc) nbl = blankS[(tn - 1) * U1 + u];
            if (ok && u >= 1 && tn >= 0 && tn < Tc) nlb = labelS[tn * Uc + (u - 1)];
        }
        int t = d - u;
        if (ok && t >= 0 && t < Tc) {
            float val;
            if (d == 0) {
                val = 0.f;
            } else {
                float x = (t >= 1) ? prev[u] + cbl : -INFINITY;
                float y = (u >= 1) ? prev[u - 1] + clb : -INFINITY;
                float hi = fmaxf(x, y), lo = fminf(x, y);
                val = (lo == -INFINITY) ? hi : hi + __logf(1.f + __expf(lo - hi));
            }
            cur[u] = val;
            if (t == tl - 1 && u == ul) llk = val;
        }
        __syncthreads();
        float* tmp = prev; prev = cur; cur = tmp;
        cbl = nbl; clb = nlb;
    }

    if (tid == 0) {
        g_ll[b] = llk + blankS[(tl - 1) * U1 + ul];
        __threadfence();
        int old = atomicAdd(&g_done, 1);
        if (old == Bc - 1) {
            volatile float* ll = g_ll;
            out[0] = -0.25f * (ll[0] + ll[1] + ll[2] + ll[3]);
            g_done = 0;
        }
    }
}

// ---------------------------------------------------------------------------
extern "C" void kernel_launch(void* const* d_in, const int* in_sizes, int n_in,
                              void* d_out, int out_size) {
    const float* enc     = (const float*)d_in[0];
    const float* dec     = (const float*)d_in[1];
    const int*   tokens  = (const int*)d_in[2];
    const int*   out_len = (const int*)d_in[3];
    const int*   tok_len = (const int*)d_in[4];
    const float* W1      = (const float*)d_in[5];
    const float* b1      = (const float*)d_in[6];
    const float* W2      = (const float*)d_in[7];
    const float* b2      = (const float*)d_in[8];
    float* out = (float*)d_out;

    cudaFuncSetAttribute(joint_mma, cudaFuncAttributeMaxDynamicSharedMemorySize, DSMEM);
    cudaFuncSetAttribute(dp_kernel, cudaFuncAttributeMaxDynamicSharedMemorySize, DP_SMEM);

    prep_kernel<<<PREP_BLKS, 256>>>(W2, enc, dec, W1, b1);
    joint_mma<<<Bc * BLKS_B, 256, DSMEM>>>(b2, tokens);
    dp_kernel<<<Bc, 128, DP_SMEM>>>(out_len, tok_len, out);
}